// round 2
// baseline (speedup 1.0000x reference)
#include <cuda_runtime.h>
#include <math.h>

#define N_NODES 50000
#define N_EDGES 800000
#define NKC     4096        // NK * COUT = 64*64
#define NSEG    8192        // NB * GRID^3 = 16*512
#define EPS_BN  1e-5f

// ---------------- device scratch (allocation-free rule: __device__ globals) ----------------
__device__ float g_xw[(long long)N_NODES * NKC];   // 819 MB: x @ W_k for all k
__device__ float g_agg[N_NODES * 64];
__device__ float g_h[N_NODES * 64];
__device__ float g_cnt[N_NODES];
__device__ float g_stats[128];                     // [0:64) sum, [64:128) sumsq
__device__ float g_scale[64];
__device__ float g_shift[64];

typedef unsigned long long u64;

__device__ __forceinline__ u64 fma2(u64 a, u64 b, u64 c) {
    u64 r;
    asm("fma.rn.f32x2 %0, %1, %2, %3;" : "=l"(r) : "l"(a), "l"(b), "l"(c));
    return r;
}
__device__ __forceinline__ u64 dup2(float v) {
    unsigned uv = __float_as_uint(v);
    u64 r;
    asm("mov.b64 %0, {%1, %1};" : "=l"(r) : "r"(uv));
    return r;
}

// order-preserving float <-> uint encoding for atomicMax-based segment_max
__device__ __forceinline__ unsigned encf(float f) {
    unsigned u = __float_as_uint(f);
    return (u & 0x80000000u) ? ~u : (u | 0x80000000u);
}
__device__ __forceinline__ float decf(unsigned e) {
    return __uint_as_float((e & 0x80000000u) ? (e ^ 0x80000000u) : ~e);
}

// ---------------- init: zero accumulators + output (poisoned by harness) ----------------
__global__ void init_kernel(unsigned* __restrict__ out) {
    int i = blockIdx.x * 256 + threadIdx.x;
    if (i < N_NODES * 64) g_agg[i] = 0.f;
    if (i < N_NODES)      g_cnt[i] = 0.f;
    if (i < 128)          g_stats[i] = 0.f;
    if (i < NSEG * 64)    out[i] = 0u;   // sentinel: any finite float encodes > 0
}

// ---------------- GEMM: xw[n, k*64+d] = sum_c x[n,c] * weight[k,c,d] ----------------
// Tile 128(M) x 128(N=2 kernels), 256 threads, 8x8 outputs/thread via packed f32x2 FMA.
__global__ void __launch_bounds__(256, 2) gemm_kernel(const float* __restrict__ x,
                                                      const float* __restrict__ w) {
    extern __shared__ float sm[];
    float* As = sm;             // [64][132]  (transposed x tile, padded)
    float* Bs = sm + 64 * 132;  // [64][132]

    const int t    = threadIdx.x;
    const int m0   = blockIdx.x * 128;
    const int col0 = blockIdx.y * 128;

    // load A tile: 128 rows x 64 c, transposed into As[c][m]
    #pragma unroll
    for (int i = 0; i < 8; i++) {
        int f  = t + i * 256;          // float4 id, 2048 total
        int m  = f >> 4;
        int c4 = (f & 15) << 2;
        float4 v = make_float4(0.f, 0.f, 0.f, 0.f);
        int gm = m0 + m;
        if (gm < N_NODES) v = *reinterpret_cast<const float4*>(x + (long long)gm * 64 + c4);
        As[(c4 + 0) * 132 + m] = v.x;
        As[(c4 + 1) * 132 + m] = v.y;
        As[(c4 + 2) * 132 + m] = v.z;
        As[(c4 + 3) * 132 + m] = v.w;
    }
    // load B tile: Bs[c][j] = weight[k, c, d] with (k,d) = decode(col0 + j)
    #pragma unroll
    for (int i = 0; i < 8; i++) {
        int f  = t + i * 256;          // float4 id over 2048
        int c  = f >> 5;
        int j4 = (f & 31) << 2;        // never crosses a k boundary (64 % 4 == 0)
        int col = col0 + j4;
        int k = col >> 6, d = col & 63;
        float4 v = *reinterpret_cast<const float4*>(w + k * 4096 + c * 64 + d);
        *reinterpret_cast<float4*>(&Bs[c * 132 + j4]) = v;
    }
    __syncthreads();

    const int tx = t & 15, ty = t >> 4;
    const int r0 = ty * 8, j0 = tx * 8;

    u64 acc[4][8];
    #pragma unroll
    for (int i = 0; i < 4; i++)
        #pragma unroll
        for (int j = 0; j < 8; j++) acc[i][j] = 0ull;

    #pragma unroll 8
    for (int c = 0; c < 64; c++) {
        const float* ar = &As[c * 132 + r0];
        ulonglong2 a01 = *reinterpret_cast<const ulonglong2*>(ar);       // rows (r0, r0+1), (r0+2, r0+3)
        ulonglong2 a23 = *reinterpret_cast<const ulonglong2*>(ar + 4);   // rows (r0+4..7)
        float4 b0 = *reinterpret_cast<const float4*>(&Bs[c * 132 + j0]);
        float4 b1 = *reinterpret_cast<const float4*>(&Bs[c * 132 + j0 + 4]);
        u64 ap[4] = {a01.x, a01.y, a23.x, a23.y};
        float bv[8] = {b0.x, b0.y, b0.z, b0.w, b1.x, b1.y, b1.z, b1.w};
        #pragma unroll
        for (int j = 0; j < 8; j++) {
            u64 bd = dup2(bv[j]);
            #pragma unroll
            for (int i = 0; i < 4; i++) acc[i][j] = fma2(ap[i], bd, acc[i][j]);
        }
    }

    // store: acc[i][j] holds rows (r0+2i, r0+2i+1), col j0+j
    #pragma unroll
    for (int i = 0; i < 4; i++) {
        int gm = m0 + r0 + 2 * i;
        if (gm >= N_NODES) break;
        float2 u[8];
        #pragma unroll
        for (int j = 0; j < 8; j++) u[j] = *reinterpret_cast<float2*>(&acc[i][j]);
        float* o0 = g_xw + (long long)gm * NKC + col0 + j0;
        *reinterpret_cast<float4*>(o0)     = make_float4(u[0].x, u[1].x, u[2].x, u[3].x);
        *reinterpret_cast<float4*>(o0 + 4) = make_float4(u[4].x, u[5].x, u[6].x, u[7].x);
        if (gm + 1 < N_NODES) {
            float* o1 = o0 + NKC;
            *reinterpret_cast<float4*>(o1)     = make_float4(u[0].y, u[1].y, u[2].y, u[3].y);
            *reinterpret_cast<float4*>(o1 + 4) = make_float4(u[4].y, u[5].y, u[6].y, u[7].y);
        }
    }
}

// ---------------- edge kernel: spline-weighted gather + scatter-add ----------------
// 16 lanes per edge; lane l covers output channels [4l, 4l+4).
__global__ void __launch_bounds__(256) edge_kernel(const int* __restrict__ eidx,
                                                   const float* __restrict__ attr) {
    int t = threadIdx.x;
    int g = t >> 4;
    int l = t & 15;
    int e = blockIdx.x * 16 + g;
    if (e >= N_EDGES) return;

    int s = eidx[e];
    int d = eidx[N_EDGES + e];

    float f0 = attr[e * 3 + 0] * 3.f;
    float f1 = attr[e * 3 + 1] * 3.f;
    float f2 = attr[e * 3 + 2] * 3.f;
    float l0 = fminf(fmaxf(floorf(f0), 0.f), 2.f);
    float l1 = fminf(fmaxf(floorf(f1), 0.f), 2.f);
    float l2 = fminf(fmaxf(floorf(f2), 0.f), 2.f);
    float t0 = f0 - l0, t1 = f1 - l1, t2 = f2 - l2;
    float s0 = 1.f - t0, s1 = 1.f - t1, s2 = 1.f - t2;
    int base_k = (int)l0 + 4 * (int)l1 + 16 * (int)l2;

    const float* bp = g_xw + (long long)s * NKC + base_k * 64 + l * 4;
    float4 acc = make_float4(0.f, 0.f, 0.f, 0.f);
    #pragma unroll
    for (int b = 0; b < 8; b++) {
        int b0 = b & 1, b1 = (b >> 1) & 1, b2 = (b >> 2) & 1;
        float wgt = (b0 ? t0 : s0) * (b1 ? t1 : s1) * (b2 ? t2 : s2);
        float4 v = *reinterpret_cast<const float4*>(bp + (b0 + 4 * b1 + 16 * b2) * 64);
        acc.x += wgt * v.x; acc.y += wgt * v.y;
        acc.z += wgt * v.z; acc.w += wgt * v.w;
    }
    float* ap = g_agg + (long long)d * 64 + l * 4;
    atomicAdd(ap + 0, acc.x);
    atomicAdd(ap + 1, acc.y);
    atomicAdd(ap + 2, acc.z);
    atomicAdd(ap + 3, acc.w);
    if (l == 0) atomicAdd(&g_cnt[d], 1.f);
}

// ---------------- node kernel: mean + x@root + bias, ELU, h store, BN partial stats ----------------
__global__ void __launch_bounds__(256) node_kernel(const float* __restrict__ x,
                                                   const float* __restrict__ root,
                                                   const float* __restrict__ bias) {
    __shared__ float rs[64 * 64];
    __shared__ float sred[128];
    int t = threadIdx.x;
    for (int i = t; i < 4096; i += 256) rs[i] = root[i];
    if (t < 128) sred[t] = 0.f;
    __syncthreads();

    int lane = t & 31, warp = t >> 5;
    int gw = blockIdx.x * 8 + warp;
    int nw = gridDim.x * 8;
    int d0 = lane, d1 = lane + 32;
    float b0 = bias[d0], b1 = bias[d1];
    float su0 = 0.f, sq0 = 0.f, su1 = 0.f, sq1 = 0.f;

    for (int n = gw; n < N_NODES; n += nw) {
        float ic = 1.f / fmaxf(g_cnt[n], 1.f);
        long long off = (long long)n * 64;
        float a0 = g_agg[off + d0] * ic + b0;
        float a1 = g_agg[off + d1] * ic + b1;
        const float* xr = x + off;
        #pragma unroll 8
        for (int c = 0; c < 64; c++) {
            float xv = xr[c];
            a0 += xv * rs[c * 64 + d0];
            a1 += xv * rs[c * 64 + d1];
        }
        float h0 = a0 > 0.f ? a0 : expm1f(a0);
        float h1 = a1 > 0.f ? a1 : expm1f(a1);
        g_h[off + d0] = h0;
        g_h[off + d1] = h1;
        su0 += h0; sq0 += h0 * h0;
        su1 += h1; sq1 += h1 * h1;
    }
    atomicAdd(&sred[d0], su0);
    atomicAdd(&sred[d1], su1);
    atomicAdd(&sred[64 + d0], sq0);
    atomicAdd(&sred[64 + d1], sq1);
    __syncthreads();
    if (t < 128) atomicAdd(&g_stats[t], sred[t]);
}

// ---------------- BN finalize: per-channel scale/shift ----------------
__global__ void stats_kernel(const float* __restrict__ gamma, const float* __restrict__ beta) {
    int d = threadIdx.x;
    if (d < 64) {
        float mean = g_stats[d] * (1.f / N_NODES);
        float var  = g_stats[64 + d] * (1.f / N_NODES) - mean * mean;
        float inv  = rsqrtf(var + EPS_BN);
        float sc   = gamma[d] * inv;
        g_scale[d] = sc;
        g_shift[d] = beta[d] - mean * sc;
    }
}

// ---------------- voxel max pool via atomicMax on encoded floats ----------------
__global__ void __launch_bounds__(256) pool_kernel(const float* __restrict__ pos,
                                                   const int* __restrict__ batch,
                                                   unsigned* __restrict__ outp) {
    int t = threadIdx.x;
    int lane = t & 31, warp = t >> 5;
    int gw = blockIdx.x * 8 + warp;
    int nw = gridDim.x * 8;
    int d0 = lane, d1 = lane + 32;
    float sc0 = g_scale[d0], sc1 = g_scale[d1];
    float sh0 = g_shift[d0], sh1 = g_shift[d1];

    for (int n = gw; n < N_NODES; n += nw) {
        float p0 = pos[n * 3 + 0], p1 = pos[n * 3 + 1], p2 = pos[n * 3 + 2];
        int v0 = min(max((int)floorf(p0 * (1.f / 32.f)), 0), 7);
        int v1 = min(max((int)floorf(p1 * (1.f / 32.f)), 0), 7);
        int v2 = min(max((int)floorf(p2 * (1.f / 32.f)), 0), 7);
        int cl = batch[n] * 512 + v0 * 64 + v1 * 8 + v2;
        long long off = (long long)n * 64;
        unsigned* op = outp + (long long)cl * 64;
        float y0 = g_h[off + d0] * sc0 + sh0;
        float y1 = g_h[off + d1] * sc1 + sh1;
        atomicMax(op + d0, encf(y0));
        atomicMax(op + d1, encf(y1));
    }
}

// ---------------- decode encoded maxima; empty voxels (sentinel 0) -> 0 ----------------
__global__ void decode_kernel(float* __restrict__ out) {
    int i = blockIdx.x * 256 + threadIdx.x;
    if (i < NSEG * 64) {
        unsigned u = reinterpret_cast<unsigned*>(out)[i];
        out[i] = u ? decf(u) : 0.f;
    }
}

// ---------------- launch ----------------
extern "C" void kernel_launch(void* const* d_in, const int* in_sizes, int n_in,
                              void* d_out, int out_size) {
    const float* x      = (const float*)d_in[0];
    const int*   eidx   = (const int*)  d_in[1];
    const float* attr   = (const float*)d_in[2];
    const float* pos    = (const float*)d_in[3];
    const int*   batch  = (const int*)  d_in[4];
    const float* weight = (const float*)d_in[5];
    const float* root   = (const float*)d_in[6];
    const float* bias   = (const float*)d_in[7];
    const float* gamma  = (const float*)d_in[8];
    const float* beta   = (const float*)d_in[9];

    cudaFuncSetAttribute(gemm_kernel, cudaFuncAttributeMaxDynamicSharedMemorySize, 67584);

    init_kernel<<<12500, 256>>>((unsigned*)d_out);

    dim3 gg((N_NODES + 127) / 128, 32);
    gemm_kernel<<<gg, 256, 67584>>>(x, weight);

    edge_kernel<<<N_EDGES / 16, 256>>>(eidx, attr);
    node_kernel<<<256, 256>>>(x, root, bias);
    stats_kernel<<<1, 64>>>(gamma, beta);
    pool_kernel<<<256, 256>>>(pos, batch, (unsigned*)d_out);
    decode_kernel<<<(NSEG * 64 + 255) / 256, 256>>>((float*)d_out);
}

// round 3
// speedup vs baseline: 1.2787x; 1.2787x over previous
#include <cuda_runtime.h>
#include <cuda_fp16.h>
#include <math.h>

#define N_NODES 50000
#define N_EDGES 800000
#define NKC     4096        // NK * COUT = 64*64
#define NSEG    8192        // NB * GRID^3 = 16*512
#define EPS_BN  1e-5f

// ---------------- device scratch (allocation-free rule: __device__ globals) ----------------
__device__ __half g_xw[(long long)N_NODES * NKC];  // 410 MB: x @ W_k for all k (fp16)
__device__ float g_agg[N_NODES * 64];
__device__ float g_h[N_NODES * 64];
__device__ float g_cnt[N_NODES];
__device__ float g_stats[128];                     // [0:64) sum, [64:128) sumsq
__device__ float g_scale[64];
__device__ float g_shift[64];

typedef unsigned long long u64;

__device__ __forceinline__ u64 fma2(u64 a, u64 b, u64 c) {
    u64 r;
    asm("fma.rn.f32x2 %0, %1, %2, %3;" : "=l"(r) : "l"(a), "l"(b), "l"(c));
    return r;
}
__device__ __forceinline__ u64 dup2(float v) {
    unsigned uv = __float_as_uint(v);
    u64 r;
    asm("mov.b64 %0, {%1, %1};" : "=l"(r) : "r"(uv));
    return r;
}
__device__ __forceinline__ void red_add_v4(float* p, float a, float b, float c, float d) {
    asm volatile("red.global.add.v4.f32 [%0], {%1, %2, %3, %4};"
                 :: "l"(p), "f"(a), "f"(b), "f"(c), "f"(d) : "memory");
}
__device__ __forceinline__ void red_add_f32(float* p, float a) {
    asm volatile("red.global.add.f32 [%0], %1;" :: "l"(p), "f"(a) : "memory");
}

// order-preserving float <-> uint encoding for atomicMax-based segment_max
__device__ __forceinline__ unsigned encf(float f) {
    unsigned u = __float_as_uint(f);
    return (u & 0x80000000u) ? ~u : (u | 0x80000000u);
}
__device__ __forceinline__ float decf(unsigned e) {
    return __uint_as_float((e & 0x80000000u) ? (e ^ 0x80000000u) : ~e);
}

// ---------------- init: zero accumulators + output (poisoned by harness) ----------------
__global__ void init_kernel(unsigned* __restrict__ out) {
    int i = blockIdx.x * 256 + threadIdx.x;
    if (i < N_NODES * 64) g_agg[i] = 0.f;
    if (i < N_NODES)      g_cnt[i] = 0.f;
    if (i < 128)          g_stats[i] = 0.f;
    if (i < NSEG * 64)    out[i] = 0u;   // sentinel: any finite float encodes > 0
}

// ---------------- GEMM: xw[n, k*64+d] = sum_c x[n,c] * weight[k,c,d] (fp16 out) ----------
// Tile 128(M) x 128(cols), 256 threads, 8x8 outputs/thread via packed f32x2 FMA.
__global__ void __launch_bounds__(256, 2) gemm_kernel(const float* __restrict__ x,
                                                      const float* __restrict__ w) {
    extern __shared__ float sm[];
    float* As = sm;             // [64][132]  (transposed x tile, padded)
    float* Bs = sm + 64 * 132;  // [64][132]

    const int t    = threadIdx.x;
    const int m0   = blockIdx.x * 128;
    const int col0 = blockIdx.y * 128;

    #pragma unroll
    for (int i = 0; i < 8; i++) {
        int f  = t + i * 256;
        int m  = f >> 4;
        int c4 = (f & 15) << 2;
        float4 v = make_float4(0.f, 0.f, 0.f, 0.f);
        int gm = m0 + m;
        if (gm < N_NODES) v = *reinterpret_cast<const float4*>(x + (long long)gm * 64 + c4);
        As[(c4 + 0) * 132 + m] = v.x;
        As[(c4 + 1) * 132 + m] = v.y;
        As[(c4 + 2) * 132 + m] = v.z;
        As[(c4 + 3) * 132 + m] = v.w;
    }
    #pragma unroll
    for (int i = 0; i < 8; i++) {
        int f  = t + i * 256;
        int c  = f >> 5;
        int j4 = (f & 31) << 2;
        int col = col0 + j4;
        int k = col >> 6, d = col & 63;
        float4 v = *reinterpret_cast<const float4*>(w + k * 4096 + c * 64 + d);
        *reinterpret_cast<float4*>(&Bs[c * 132 + j4]) = v;
    }
    __syncthreads();

    const int tx = t & 15, ty = t >> 4;
    const int r0 = ty * 8, j0 = tx * 8;

    u64 acc[4][8];
    #pragma unroll
    for (int i = 0; i < 4; i++)
        #pragma unroll
        for (int j = 0; j < 8; j++) acc[i][j] = 0ull;

    #pragma unroll 8
    for (int c = 0; c < 64; c++) {
        const float* ar = &As[c * 132 + r0];
        ulonglong2 a01 = *reinterpret_cast<const ulonglong2*>(ar);
        ulonglong2 a23 = *reinterpret_cast<const ulonglong2*>(ar + 4);
        float4 b0 = *reinterpret_cast<const float4*>(&Bs[c * 132 + j0]);
        float4 b1 = *reinterpret_cast<const float4*>(&Bs[c * 132 + j0 + 4]);
        u64 ap[4] = {a01.x, a01.y, a23.x, a23.y};
        float bv[8] = {b0.x, b0.y, b0.z, b0.w, b1.x, b1.y, b1.z, b1.w};
        #pragma unroll
        for (int j = 0; j < 8; j++) {
            u64 bd = dup2(bv[j]);
            #pragma unroll
            for (int i = 0; i < 4; i++) acc[i][j] = fma2(ap[i], bd, acc[i][j]);
        }
    }

    // store fp16: acc[i][j] holds rows (r0+2i, r0+2i+1), col j0+j
    #pragma unroll
    for (int i = 0; i < 4; i++) {
        int gm = m0 + r0 + 2 * i;
        if (gm >= N_NODES) break;
        float2 u[8];
        #pragma unroll
        for (int j = 0; j < 8; j++) u[j] = *reinterpret_cast<float2*>(&acc[i][j]);
        __half2 r0h[4], r1h[4];
        #pragma unroll
        for (int j = 0; j < 4; j++) {
            r0h[j] = __floats2half2_rn(u[2 * j].x, u[2 * j + 1].x);
            r1h[j] = __floats2half2_rn(u[2 * j].y, u[2 * j + 1].y);
        }
        __half* o0 = g_xw + (long long)gm * NKC + col0 + j0;
        *reinterpret_cast<uint4*>(o0) = *reinterpret_cast<uint4*>(r0h);
        if (gm + 1 < N_NODES)
            *reinterpret_cast<uint4*>(o0 + NKC) = *reinterpret_cast<uint4*>(r1h);
    }
}

// ---------------- edge kernel: spline-weighted gather + scatter-add ----------------
// 8 lanes per edge; lane l covers output channels [8l, 8l+8).
__global__ void __launch_bounds__(256) edge_kernel(const int* __restrict__ eidx,
                                                   const float* __restrict__ attr) {
    int t = threadIdx.x;
    int g = t >> 3;
    int l = t & 7;
    int e = blockIdx.x * 32 + g;
    if (e >= N_EDGES) return;

    int s = eidx[e];
    int d = eidx[N_EDGES + e];

    float f0 = attr[e * 3 + 0] * 3.f;
    float f1 = attr[e * 3 + 1] * 3.f;
    float f2 = attr[e * 3 + 2] * 3.f;
    float l0 = fminf(fmaxf(floorf(f0), 0.f), 2.f);
    float l1 = fminf(fmaxf(floorf(f1), 0.f), 2.f);
    float l2 = fminf(fmaxf(floorf(f2), 0.f), 2.f);
    float t0 = f0 - l0, t1 = f1 - l1, t2 = f2 - l2;
    float s0 = 1.f - t0, s1 = 1.f - t1, s2 = 1.f - t2;
    int base_k = (int)l0 + 4 * (int)l1 + 16 * (int)l2;

    const __half* bp = g_xw + (long long)s * NKC + base_k * 64 + l * 8;

    // issue all 8 independent 16B loads first (MLP), then math
    uint4 q[8];
    #pragma unroll
    for (int b = 0; b < 8; b++) {
        int b0 = b & 1, b1 = (b >> 1) & 1, b2 = (b >> 2) & 1;
        q[b] = *reinterpret_cast<const uint4*>(bp + (b0 + 4 * b1 + 16 * b2) * 64);
    }

    float acc[8] = {0.f, 0.f, 0.f, 0.f, 0.f, 0.f, 0.f, 0.f};
    #pragma unroll
    for (int b = 0; b < 8; b++) {
        int b0 = b & 1, b1 = (b >> 1) & 1, b2 = (b >> 2) & 1;
        float wgt = (b0 ? t0 : s0) * (b1 ? t1 : s1) * (b2 ? t2 : s2);
        const __half2* h = reinterpret_cast<const __half2*>(&q[b]);
        #pragma unroll
        for (int j = 0; j < 4; j++) {
            float2 f = __half22float2(h[j]);
            acc[2 * j]     += wgt * f.x;
            acc[2 * j + 1] += wgt * f.y;
        }
    }
    float* ap = g_agg + (long long)d * 64 + l * 8;
    red_add_v4(ap,     acc[0], acc[1], acc[2], acc[3]);
    red_add_v4(ap + 4, acc[4], acc[5], acc[6], acc[7]);
    if (l == 0) red_add_f32(&g_cnt[d], 1.f);
}

// ---------------- node kernel: mean + x@root + bias, ELU, h store, BN partial stats ----------
__global__ void __launch_bounds__(256) node_kernel(const float* __restrict__ x,
                                                   const float* __restrict__ root,
                                                   const float* __restrict__ bias) {
    __shared__ float rs[64 * 64];
    __shared__ float sred[128];
    int t = threadIdx.x;
    for (int i = t; i < 4096; i += 256) rs[i] = root[i];
    if (t < 128) sred[t] = 0.f;
    __syncthreads();

    int lane = t & 31, warp = t >> 5;
    int gw = blockIdx.x * 8 + warp;
    int nw = gridDim.x * 8;
    int d0 = lane, d1 = lane + 32;
    float b0 = bias[d0], b1 = bias[d1];
    float su0 = 0.f, sq0 = 0.f, su1 = 0.f, sq1 = 0.f;

    for (int n = gw; n < N_NODES; n += nw) {
        float ic = 1.f / fmaxf(g_cnt[n], 1.f);
        long long off = (long long)n * 64;
        float a0 = g_agg[off + d0] * ic + b0;
        float a1 = g_agg[off + d1] * ic + b1;
        const float* xr = x + off;
        #pragma unroll 16
        for (int c = 0; c < 64; c++) {
            float xv = xr[c];
            a0 += xv * rs[c * 64 + d0];
            a1 += xv * rs[c * 64 + d1];
        }
        float h0 = a0 > 0.f ? a0 : expm1f(a0);
        float h1 = a1 > 0.f ? a1 : expm1f(a1);
        g_h[off + d0] = h0;
        g_h[off + d1] = h1;
        su0 += h0; sq0 += h0 * h0;
        su1 += h1; sq1 += h1 * h1;
    }
    atomicAdd(&sred[d0], su0);
    atomicAdd(&sred[d1], su1);
    atomicAdd(&sred[64 + d0], sq0);
    atomicAdd(&sred[64 + d1], sq1);
    __syncthreads();
    if (t < 128) atomicAdd(&g_stats[t], sred[t]);
}

// ---------------- BN finalize: per-channel scale/shift ----------------
__global__ void stats_kernel(const float* __restrict__ gamma, const float* __restrict__ beta) {
    int d = threadIdx.x;
    if (d < 64) {
        float mean = g_stats[d] * (1.f / N_NODES);
        float var  = g_stats[64 + d] * (1.f / N_NODES) - mean * mean;
        float inv  = rsqrtf(var + EPS_BN);
        float sc   = gamma[d] * inv;
        g_scale[d] = sc;
        g_shift[d] = beta[d] - mean * sc;
    }
}

// ---------------- voxel max pool via atomicMax on encoded floats ----------------
__global__ void __launch_bounds__(256) pool_kernel(const float* __restrict__ pos,
                                                   const int* __restrict__ batch,
                                                   unsigned* __restrict__ outp) {
    int t = threadIdx.x;
    int lane = t & 31, warp = t >> 5;
    int gw = blockIdx.x * 8 + warp;
    int nw = gridDim.x * 8;
    int d0 = lane, d1 = lane + 32;
    float sc0 = g_scale[d0], sc1 = g_scale[d1];
    float sh0 = g_shift[d0], sh1 = g_shift[d1];

    for (int n = gw; n < N_NODES; n += nw) {
        float p0 = pos[n * 3 + 0], p1 = pos[n * 3 + 1], p2 = pos[n * 3 + 2];
        int v0 = min(max((int)floorf(p0 * (1.f / 32.f)), 0), 7);
        int v1 = min(max((int)floorf(p1 * (1.f / 32.f)), 0), 7);
        int v2 = min(max((int)floorf(p2 * (1.f / 32.f)), 0), 7);
        int cl = batch[n] * 512 + v0 * 64 + v1 * 8 + v2;
        long long off = (long long)n * 64;
        unsigned* op = outp + (long long)cl * 64;
        float y0 = g_h[off + d0] * sc0 + sh0;
        float y1 = g_h[off + d1] * sc1 + sh1;
        atomicMax(op + d0, encf(y0));
        atomicMax(op + d1, encf(y1));
    }
}

// ---------------- decode encoded maxima; empty voxels (sentinel 0) -> 0 ----------------
__global__ void decode_kernel(float* __restrict__ out) {
    int i = blockIdx.x * 256 + threadIdx.x;
    if (i < NSEG * 64) {
        unsigned u = reinterpret_cast<unsigned*>(out)[i];
        out[i] = u ? decf(u) : 0.f;
    }
}

// ---------------- launch ----------------
extern "C" void kernel_launch(void* const* d_in, const int* in_sizes, int n_in,
                              void* d_out, int out_size) {
    const float* x      = (const float*)d_in[0];
    const int*   eidx   = (const int*)  d_in[1];
    const float* attr   = (const float*)d_in[2];
    const float* pos    = (const float*)d_in[3];
    const int*   batch  = (const int*)  d_in[4];
    const float* weight = (const float*)d_in[5];
    const float* root   = (const float*)d_in[6];
    const float* bias   = (const float*)d_in[7];
    const float* gamma  = (const float*)d_in[8];
    const float* beta   = (const float*)d_in[9];

    cudaFuncSetAttribute(gemm_kernel, cudaFuncAttributeMaxDynamicSharedMemorySize, 67584);

    init_kernel<<<12500, 256>>>((unsigned*)d_out);

    dim3 gg((N_NODES + 127) / 128, 32);
    gemm_kernel<<<gg, 256, 67584>>>(x, weight);

    edge_kernel<<<N_EDGES / 32, 256>>>(eidx, attr);
    node_kernel<<<800, 256>>>(x, root, bias);
    stats_kernel<<<1, 64>>>(gamma, beta);
    pool_kernel<<<512, 256>>>(pos, batch, (unsigned*)d_out);
    decode_kernel<<<(NSEG * 64 + 255) / 256, 256>>>((float*)d_out);
}

// round 5
// speedup vs baseline: 2.8162x; 2.2023x over previous
#include <cuda_runtime.h>
#include <cuda_fp16.h>
#include <math.h>
#include <cstdint>

#define N_NODES 50000
#define N_EDGES 800000
#define NKC     4096        // NK * COUT = 64*64
#define NSEG    8192        // NB * GRID^3
#define EPS_BN  1e-5f

// ---------------- device scratch ----------------
__device__ __half g_xw[(long long)N_NODES * NKC];   // 410 MB fp16: x @ W_k
__device__ __half g_xh[N_NODES * 64];               // x in fp16
__device__ __half g_wt[NKC * 64];                   // transposed weight [col][c] fp16
__device__ float g_agg[N_NODES * 64];
__device__ float g_h[N_NODES * 64];
__device__ float g_cnt[N_NODES];
__device__ float g_stats[128];
__device__ float g_scale[64];
__device__ float g_shift[64];

// order-preserving float <-> uint encoding for atomicMax-based segment_max
__device__ __forceinline__ unsigned encf(float f) {
    unsigned u = __float_as_uint(f);
    return (u & 0x80000000u) ? ~u : (u | 0x80000000u);
}
__device__ __forceinline__ float decf(unsigned e) {
    return __uint_as_float((e & 0x80000000u) ? (e ^ 0x80000000u) : ~e);
}
__device__ __forceinline__ void red_add_v4(float* p, float a, float b, float c, float d) {
    asm volatile("red.global.add.v4.f32 [%0], {%1, %2, %3, %4};"
                 :: "l"(p), "f"(a), "f"(b), "f"(c), "f"(d) : "memory");
}
__device__ __forceinline__ void red_add_f32(float* p, float a) {
    asm volatile("red.global.add.f32 [%0], %1;" :: "l"(p), "f"(a) : "memory");
}
__device__ __forceinline__ void hmma16816(float* d, const uint32_t* a, const uint32_t* b) {
    asm volatile(
        "mma.sync.aligned.m16n8k16.row.col.f32.f16.f16.f32 "
        "{%0,%1,%2,%3}, {%4,%5,%6,%7}, {%8,%9}, {%0,%1,%2,%3};"
        : "+f"(d[0]), "+f"(d[1]), "+f"(d[2]), "+f"(d[3])
        : "r"(a[0]), "r"(a[1]), "r"(a[2]), "r"(a[3]), "r"(b[0]), "r"(b[1]));
}

// ---------------- init ----------------
__global__ void init_kernel(unsigned* __restrict__ out) {
    int i = blockIdx.x * 256 + threadIdx.x;
    if (i < N_NODES * 64) g_agg[i] = 0.f;
    if (i < N_NODES)      g_cnt[i] = 0.f;
    if (i < 128)          g_stats[i] = 0.f;
    if (i < NSEG * 64)    out[i] = 0u;
}

// ---------------- fp16 conversions ----------------
__global__ void cvt_x_kernel(const float* __restrict__ x) {
    int i = blockIdx.x * 256 + threadIdx.x;
    if (i < N_NODES * 64) g_xh[i] = __float2half_rn(x[i]);
}
__global__ void cvt_w_kernel(const float* __restrict__ w) {
    int i = blockIdx.x * 256 + threadIdx.x;   // i = col*64 + c
    if (i < NKC * 64) {
        int col = i >> 6, c = i & 63;
        int k = col >> 6, d = col & 63;
        g_wt[i] = __float2half_rn(w[k * 4096 + c * 64 + d]);
    }
}

// ---------------- HMMA GEMM: g_xw[m, col] = sum_c xh[m,c] * wt[col,c] ----------------
// Block tile M=128 x N=128, K=64. 8 warps: 4 along M (32 rows) x 2 along N (64 cols).
// Each warp: 2 m-frags x 8 n-frags of m16n8k16, 4 k-steps.
#define APAD 72   // halves per smem row (conflict-free: bank = 4g + tg)
#define CPAD 136  // C staging stride in halves

__global__ void __launch_bounds__(256) mm_kernel() {
    __shared__ __half sA[128 * APAD];
    __shared__ __half sB[128 * APAD];

    const int t = threadIdx.x;
    const int m0 = blockIdx.x * 128;
    const int col0 = blockIdx.y * 128;

    // load A tile (128 x 64 halves), 16B per thread-iter
    #pragma unroll
    for (int i = 0; i < 4; i++) {
        int f = t + i * 256;           // 1024 uint4 total
        int m = f >> 3;
        int c8 = (f & 7) * 8;
        uint4 v = make_uint4(0, 0, 0, 0);
        if (m0 + m < N_NODES)
            v = *reinterpret_cast<const uint4*>(g_xh + (long long)(m0 + m) * 64 + c8);
        *reinterpret_cast<uint4*>(sA + m * APAD + c8) = v;
    }
    // load B tile (128 cols x 64 halves)
    #pragma unroll
    for (int i = 0; i < 4; i++) {
        int f = t + i * 256;
        int j = f >> 3;
        int c8 = (f & 7) * 8;
        uint4 v = *reinterpret_cast<const uint4*>(g_wt + (long long)(col0 + j) * 64 + c8);
        *reinterpret_cast<uint4*>(sB + j * APAD + c8) = v;
    }
    __syncthreads();

    const int warp = t >> 5, lane = t & 31;
    const int wm = (warp & 3) * 32;     // warp m-offset
    const int wn = (warp >> 2) * 64;    // warp n-offset
    const int g = lane >> 2, tg = lane & 3;

    float acc[2][8][4];
    #pragma unroll
    for (int mf = 0; mf < 2; mf++)
        #pragma unroll
        for (int nf = 0; nf < 8; nf++)
            #pragma unroll
            for (int q = 0; q < 4; q++) acc[mf][nf][q] = 0.f;

    #pragma unroll
    for (int ks = 0; ks < 4; ks++) {
        int k0 = ks * 16;
        uint32_t a[2][4];
        #pragma unroll
        for (int mf = 0; mf < 2; mf++) {
            int r = wm + mf * 16;
            a[mf][0] = *reinterpret_cast<const uint32_t*>(sA + (r + g)     * APAD + k0 + 2 * tg);
            a[mf][1] = *reinterpret_cast<const uint32_t*>(sA + (r + g + 8) * APAD + k0 + 2 * tg);
            a[mf][2] = *reinterpret_cast<const uint32_t*>(sA + (r + g)     * APAD + k0 + 2 * tg + 8);
            a[mf][3] = *reinterpret_cast<const uint32_t*>(sA + (r + g + 8) * APAD + k0 + 2 * tg + 8);
        }
        #pragma unroll
        for (int nf = 0; nf < 8; nf++) {
            int nb = wn + nf * 8;
            uint32_t b[2];
            b[0] = *reinterpret_cast<const uint32_t*>(sB + (nb + g) * APAD + k0 + 2 * tg);
            b[1] = *reinterpret_cast<const uint32_t*>(sB + (nb + g) * APAD + k0 + 2 * tg + 8);
            hmma16816(acc[0][nf], a[0], b);
            hmma16816(acc[1][nf], a[1], b);
        }
    }

    // stage C in smem (fp16), then coalesced 16B global stores
    __syncthreads();   // done reading sA/sB
    __half* sC = sA;   // reuse: need 128*136*2 = 34816 B <= 36864 B
    #pragma unroll
    for (int mf = 0; mf < 2; mf++) {
        #pragma unroll
        for (int nf = 0; nf < 8; nf++) {
            int c = wn + nf * 8 + 2 * tg;
            __half2 lo = __floats2half2_rn(acc[mf][nf][0], acc[mf][nf][1]);
            __half2 hi = __floats2half2_rn(acc[mf][nf][2], acc[mf][nf][3]);
            *reinterpret_cast<__half2*>(sC + (wm + mf * 16 + g)     * CPAD + c) = lo;
            *reinterpret_cast<__half2*>(sC + (wm + mf * 16 + g + 8) * CPAD + c) = hi;
        }
    }
    __syncthreads();
    #pragma unroll
    for (int i = 0; i < 8; i++) {
        int f = t + i * 256;           // 2048 uint4 total
        int row = f >> 4;
        int q8 = (f & 15) * 8;
        if (m0 + row < N_NODES) {
            uint4 v = *reinterpret_cast<const uint4*>(sC + row * CPAD + q8);
            *reinterpret_cast<uint4*>(g_xw + (long long)(m0 + row) * NKC + col0 + q8) = v;
        }
    }
}

// ---------------- edge kernel: spline-weighted gather + scatter-add ----------------
__global__ void __launch_bounds__(256) edge_kernel(const int* __restrict__ eidx,
                                                   const float* __restrict__ attr) {
    int t = threadIdx.x;
    int g = t >> 3;
    int l = t & 7;
    int e = blockIdx.x * 32 + g;
    if (e >= N_EDGES) return;

    int s = eidx[e];
    int d = eidx[N_EDGES + e];

    float f0 = attr[e * 3 + 0] * 3.f;
    float f1 = attr[e * 3 + 1] * 3.f;
    float f2 = attr[e * 3 + 2] * 3.f;
    float l0 = fminf(fmaxf(floorf(f0), 0.f), 2.f);
    float l1 = fminf(fmaxf(floorf(f1), 0.f), 2.f);
    float l2 = fminf(fmaxf(floorf(f2), 0.f), 2.f);
    float t0 = f0 - l0, t1 = f1 - l1, t2 = f2 - l2;
    float s0 = 1.f - t0, s1 = 1.f - t1, s2 = 1.f - t2;
    int base_k = (int)l0 + 4 * (int)l1 + 16 * (int)l2;

    const __half* bp = g_xw + (long long)s * NKC + base_k * 64 + l * 8;

    uint4 q[8];
    #pragma unroll
    for (int b = 0; b < 8; b++) {
        int b0 = b & 1, b1 = (b >> 1) & 1, b2 = (b >> 2) & 1;
        q[b] = *reinterpret_cast<const uint4*>(bp + (b0 + 4 * b1 + 16 * b2) * 64);
    }

    float acc[8] = {0.f, 0.f, 0.f, 0.f, 0.f, 0.f, 0.f, 0.f};
    #pragma unroll
    for (int b = 0; b < 8; b++) {
        int b0 = b & 1, b1 = (b >> 1) & 1, b2 = (b >> 2) & 1;
        float wgt = (b0 ? t0 : s0) * (b1 ? t1 : s1) * (b2 ? t2 : s2);
        const __half2* h = reinterpret_cast<const __half2*>(&q[b]);
        #pragma unroll
        for (int j = 0; j < 4; j++) {
            float2 f = __half22float2(h[j]);
            acc[2 * j]     += wgt * f.x;
            acc[2 * j + 1] += wgt * f.y;
        }
    }
    float* ap = g_agg + (long long)d * 64 + l * 8;
    red_add_v4(ap,     acc[0], acc[1], acc[2], acc[3]);
    red_add_v4(ap + 4, acc[4], acc[5], acc[6], acc[7]);
    if (l == 0) red_add_f32(&g_cnt[d], 1.f);
}

// ---------------- node kernel ----------------
__global__ void __launch_bounds__(256) node_kernel(const float* __restrict__ x,
                                                   const float* __restrict__ root,
                                                   const float* __restrict__ bias) {
    __shared__ float rs[64 * 64];
    __shared__ float sred[128];
    int t = threadIdx.x;
    for (int i = t; i < 4096; i += 256) rs[i] = root[i];
    if (t < 128) sred[t] = 0.f;
    __syncthreads();

    int lane = t & 31, warp = t >> 5;
    int gw = blockIdx.x * 8 + warp;
    int nw = gridDim.x * 8;
    int d0 = lane, d1 = lane + 32;
    float b0 = bias[d0], b1 = bias[d1];
    float su0 = 0.f, sq0 = 0.f, su1 = 0.f, sq1 = 0.f;

    for (int n = gw; n < N_NODES; n += nw) {
        float ic = 1.f / fmaxf(g_cnt[n], 1.f);
        long long off = (long long)n * 64;
        float a0 = g_agg[off + d0] * ic + b0;
        float a1 = g_agg[off + d1] * ic + b1;
        const float* xr = x + off;
        float xv0 = xr[lane], xv1 = xr[lane + 32];
        #pragma unroll
        for (int c = 0; c < 32; c++) {
            float xa = __shfl_sync(0xffffffffu, xv0, c);
            a0 += xa * rs[c * 64 + d0];
            a1 += xa * rs[c * 64 + d1];
        }
        #pragma unroll
        for (int c = 0; c < 32; c++) {
            float xa = __shfl_sync(0xffffffffu, xv1, c);
            a0 += xa * rs[(c + 32) * 64 + d0];
            a1 += xa * rs[(c + 32) * 64 + d1];
        }
        float h0 = a0 > 0.f ? a0 : expm1f(a0);
        float h1 = a1 > 0.f ? a1 : expm1f(a1);
        g_h[off + d0] = h0;
        g_h[off + d1] = h1;
        su0 += h0; sq0 += h0 * h0;
        su1 += h1; sq1 += h1 * h1;
    }
    atomicAdd(&sred[d0], su0);
    atomicAdd(&sred[d1], su1);
    atomicAdd(&sred[64 + d0], sq0);
    atomicAdd(&sred[64 + d1], sq1);
    __syncthreads();
    if (t < 128) atomicAdd(&g_stats[t], sred[t]);
}

// ---------------- BN finalize ----------------
__global__ void stats_kernel(const float* __restrict__ gamma, const float* __restrict__ beta) {
    int d = threadIdx.x;
    if (d < 64) {
        float mean = g_stats[d] * (1.f / N_NODES);
        float var  = g_stats[64 + d] * (1.f / N_NODES) - mean * mean;
        float inv  = rsqrtf(var + EPS_BN);
        float sc   = gamma[d] * inv;
        g_scale[d] = sc;
        g_shift[d] = beta[d] - mean * sc;
    }
}

// ---------------- voxel max pool ----------------
__global__ void __launch_bounds__(256) pool_kernel(const float* __restrict__ pos,
                                                   const int* __restrict__ batch,
                                                   unsigned* __restrict__ outp) {
    int t = threadIdx.x;
    int lane = t & 31, warp = t >> 5;
    int gw = blockIdx.x * 8 + warp;
    int nw = gridDim.x * 8;
    int d0 = lane, d1 = lane + 32;
    float sc0 = g_scale[d0], sc1 = g_scale[d1];
    float sh0 = g_shift[d0], sh1 = g_shift[d1];

    for (int n = gw; n < N_NODES; n += nw) {
        float p0 = pos[n * 3 + 0], p1 = pos[n * 3 + 1], p2 = pos[n * 3 + 2];
        int v0 = min(max((int)floorf(p0 * (1.f / 32.f)), 0), 7);
        int v1 = min(max((int)floorf(p1 * (1.f / 32.f)), 0), 7);
        int v2 = min(max((int)floorf(p2 * (1.f / 32.f)), 0), 7);
        int cl = batch[n] * 512 + v0 * 64 + v1 * 8 + v2;
        long long off = (long long)n * 64;
        unsigned* op = outp + (long long)cl * 64;
        float y0 = g_h[off + d0] * sc0 + sh0;
        float y1 = g_h[off + d1] * sc1 + sh1;
        atomicMax(op + d0, encf(y0));
        atomicMax(op + d1, encf(y1));
    }
}

// ---------------- decode ----------------
__global__ void decode_kernel(float* __restrict__ out) {
    int i = blockIdx.x * 256 + threadIdx.x;
    if (i < NSEG * 64) {
        unsigned u = reinterpret_cast<unsigned*>(out)[i];
        out[i] = u ? decf(u) : 0.f;
    }
}

// ---------------- launch ----------------
extern "C" void kernel_launch(void* const* d_in, const int* in_sizes, int n_in,
                              void* d_out, int out_size) {
    const float* x      = (const float*)d_in[0];
    const int*   eidx   = (const int*)  d_in[1];
    const float* attr   = (const float*)d_in[2];
    const float* pos    = (const float*)d_in[3];
    const int*   batch  = (const int*)  d_in[4];
    const float* weight = (const float*)d_in[5];
    const float* root   = (const float*)d_in[6];
    const float* bias   = (const float*)d_in[7];
    const float* gamma  = (const float*)d_in[8];
    const float* beta   = (const float*)d_in[9];

    init_kernel<<<12500, 256>>>((unsigned*)d_out);
    cvt_x_kernel<<<(N_NODES * 64 + 255) / 256, 256>>>(x);
    cvt_w_kernel<<<(NKC * 64 + 255) / 256, 256>>>(weight);

    dim3 gg((N_NODES + 127) / 128, NKC / 128);   // 391 x 32
    mm_kernel<<<gg, 256>>>();

    edge_kernel<<<N_EDGES / 32, 256>>>(eidx, attr);
    node_kernel<<<800, 256>>>(x, root, bias);
    stats_kernel<<<1, 64>>>(gamma, beta);
    pool_kernel<<<512, 256>>>(pos, batch, (unsigned*)d_out);
    decode_kernel<<<(NSEG * 64 + 255) / 256, 256>>>((float*)d_out);
}